// round 1
// baseline (speedup 1.0000x reference)
#include <cuda_runtime.h>
#include <math.h>

// ---------------------------------------------------------------------------
// Problem constants
// ---------------------------------------------------------------------------
constexpr int NN  = 30000;    // nodes per type
constexpr int NE  = 400000;   // edges per relation
constexpr int NR  = 10;       // relations
constexpr int NT  = 4;        // node types
constexpr int C1  = 128;      // layer1 channels
constexpr int H1  = 8;        // layer1 heads
constexpr int IN1 = 256;      // layer1 input dim
constexpr int C2  = 32;       // layer2 channels

__constant__ int c_SRC[NR]    = {0,1,2,3,0,1,2,1,3,1};
__constant__ int c_DST[NR]    = {0,1,2,3,1,0,1,2,1,3};
__constant__ int c_GRPOFF[5]  = {0,2,6,8,10};
__constant__ int c_GRP[NR]    = {0,5, 1,4,6,8, 2,7, 3,9};

// ---------------------------------------------------------------------------
// Scratch (static device arrays: allocation-free)
// ---------------------------------------------------------------------------
__device__ float g_h1   [NT*NN*C1];     // projected features, layer 1
__device__ float g_asrc1[NR*NN*H1];
__device__ float g_adst1[NR*NN*H1];
__device__ float g_out1 [NR*NN*C1];     // relu(agg) per relation, layer 1
__device__ float g_x2   [NT*NN*C1];     // elu(fused) -> layer2 input
__device__ float g_h2   [NT*NN*C2];
__device__ float g_asrc2[NR*NN];
__device__ float g_adst2[NR*NN];
__device__ float g_out2 [NR*NN*C2];
__device__ float g_colsum1[NR*C1];
__device__ float g_colsum2[NR*C2];
__device__ float g_sattn1[NR];
__device__ float g_sattn2[NR];
__device__ int   g_counts [NR*NN];
__device__ int   g_offsets[NR*(NN+1)];
__device__ int   g_cursor [NR*NN];
__device__ int   g_srcs   [NR*NE];

// ---------------------------------------------------------------------------
// Zeroing (counts + colsums); graph-capturable, no memset API needed
// ---------------------------------------------------------------------------
__global__ void k_zero() {
    int i = blockIdx.x * blockDim.x + threadIdx.x;
    if (i < NR*NN) g_counts[i] = 0;
    if (i < NR*C1) g_colsum1[i] = 0.f;
    if (i < NR*C2) g_colsum2[i] = 0.f;
}

// ---------------------------------------------------------------------------
// CSR build by destination (shared by both layers)
// ---------------------------------------------------------------------------
__global__ void k_count(const int* __restrict__ edges) {
    int idx = blockIdx.x * blockDim.x + threadIdx.x;
    if (idx >= NR*NE) return;
    int e = idx / NE, i = idx - e*NE;
    int col = edges[e*2*NE + NE + i];
    atomicAdd(&g_counts[e*NN + col], 1);
}

__global__ void k_scan() {   // one block (1024 threads) per relation
    const int e = blockIdx.x;
    const int t = threadIdx.x;
    constexpr int CH = 30;   // 1024*30 = 30720 >= 30000
    int base = t * CH;
    int cnt[CH];
    int sum = 0;
#pragma unroll
    for (int i = 0; i < CH; i++) {
        int idx = base + i;
        int v = (idx < NN) ? g_counts[e*NN + idx] : 0;
        cnt[i] = v; sum += v;
    }
    __shared__ int s[1024];
    s[t] = sum; __syncthreads();
    for (int d = 1; d < 1024; d <<= 1) {
        int v = (t >= d) ? s[t-d] : 0;
        __syncthreads();
        s[t] += v;
        __syncthreads();
    }
    int run = s[t] - sum;   // exclusive prefix
#pragma unroll
    for (int i = 0; i < CH; i++) {
        int idx = base + i;
        if (idx < NN) {
            g_offsets[e*(NN+1) + idx] = run;
            g_cursor [e*NN + idx]     = run;
            run += cnt[i];
        }
    }
    if (t == 1023) g_offsets[e*(NN+1) + NN] = s[1023];
}

__global__ void k_fill(const int* __restrict__ edges) {
    int idx = blockIdx.x * blockDim.x + threadIdx.x;
    if (idx >= NR*NE) return;
    int e = idx / NE, i = idx - e*NE;
    int row = edges[e*2*NE + i];
    int col = edges[e*2*NE + NE + i];
    int pos = atomicAdd(&g_cursor[e*NN + col], 1);
    g_srcs[e*NE + pos] = row;
}

// ---------------------------------------------------------------------------
// Generic fp32 GEMM: C[MxN] = A[MxK] @ B[KxN] (+bias).
// MODE 0: store C + bias.  MODE 1: accumulate column sums of tanh(C+bias)
// into colsum (semantic-attention score path, no C store).
// BM=BN=128, BK=16, 256 threads, 8x8 microtile.
// ---------------------------------------------------------------------------
template <int MODE>
__global__ void __launch_bounds__(256)
k_gemm(const float* __restrict__ A, const float* __restrict__ B,
       const float* __restrict__ bias, float* __restrict__ C,
       int M, int Ncols, int K, long strideA, long strideC,
       float* __restrict__ colsum, int colsumStride)
{
    constexpr int BM = 128, BN = 128, BK = 16;
    __shared__ float As[BK][BM];
    __shared__ float Bs[BK][BN];

    const int z = blockIdx.z;
    A += (long)z * strideA;
    if (MODE == 0) C += (long)z * strideC;

    const int m0 = blockIdx.x * BM;
    const int n0 = blockIdx.y * BN;
    const int tid = threadIdx.x;
    const int tx = tid & 15, ty = tid >> 4;

    float acc[8][8];
#pragma unroll
    for (int i = 0; i < 8; i++)
#pragma unroll
        for (int j = 0; j < 8; j++) acc[i][j] = 0.f;

    for (int k0 = 0; k0 < K; k0 += BK) {
        // load A tile (transposed into As[k][m])
#pragma unroll
        for (int it = 0; it < 2; it++) {
            int lin = tid + it * 256;
            int m = lin >> 2, kq = lin & 3;
            float4 v = {0.f, 0.f, 0.f, 0.f};
            if (m0 + m < M)
                v = *reinterpret_cast<const float4*>(A + (long)(m0+m)*K + k0 + kq*4);
            As[kq*4+0][m] = v.x; As[kq*4+1][m] = v.y;
            As[kq*4+2][m] = v.z; As[kq*4+3][m] = v.w;
        }
        // load B tile
#pragma unroll
        for (int it = 0; it < 2; it++) {
            int lin = tid + it * 256;
            int k = lin >> 5, nq = lin & 31;
            float4 v = {0.f, 0.f, 0.f, 0.f};
            if (n0 + nq*4 + 3 < Ncols)
                v = *reinterpret_cast<const float4*>(B + (long)(k0+k)*Ncols + n0 + nq*4);
            *reinterpret_cast<float4*>(&Bs[k][nq*4]) = v;
        }
        __syncthreads();
#pragma unroll
        for (int k = 0; k < BK; k++) {
            float a[8], b[8];
#pragma unroll
            for (int i = 0; i < 8; i++) a[i] = As[k][ty*8 + i];
#pragma unroll
            for (int j = 0; j < 8; j++) b[j] = Bs[k][tx*8 + j];
#pragma unroll
            for (int i = 0; i < 8; i++)
#pragma unroll
                for (int j = 0; j < 8; j++) acc[i][j] += a[i] * b[j];
        }
        __syncthreads();
    }

    if (MODE == 0) {
#pragma unroll
        for (int i = 0; i < 8; i++) {
            int r = m0 + ty*8 + i;
            if (r >= M) continue;
#pragma unroll
            for (int j = 0; j < 8; j++) {
                int c = n0 + tx*8 + j;
                if (c < Ncols) C[(long)r*Ncols + c] = acc[i][j] + bias[c];
            }
        }
    } else {
        __shared__ float cs[BN];
        if (tid < BN) cs[tid] = 0.f;
        __syncthreads();
#pragma unroll
        for (int j = 0; j < 8; j++) {
            int c = n0 + tx*8 + j;
            if (c < Ncols) {
                float bb = bias[c];
                float p = 0.f;
#pragma unroll
                for (int i = 0; i < 8; i++) {
                    int r = m0 + ty*8 + i;
                    if (r < M) p += tanhf(acc[i][j] + bb);
                }
                atomicAdd(&cs[tx*8 + j], p);
            }
        }
        __syncthreads();
        if (tid < BN && n0 + tid < Ncols)
            atomicAdd(&colsum[z*colsumStride + n0 + tid], cs[tid]);
    }
}

// ---------------------------------------------------------------------------
// Attention logits, layer 1: warp per (relation, node)
// ---------------------------------------------------------------------------
__global__ void k_logits1(const float* __restrict__ att_src,
                          const float* __restrict__ att_dst)
{
    int e = blockIdx.y;
    int n = blockIdx.x * 8 + (threadIdx.x >> 5);
    if (n >= NN) return;
    int l = threadIdx.x & 31;

    const float4* hs = reinterpret_cast<const float4*>(g_h1 + c_SRC[e]*NN*C1 + n*C1);
    const float4* hd = reinterpret_cast<const float4*>(g_h1 + c_DST[e]*NN*C1 + n*C1);
    const float4* as = reinterpret_cast<const float4*>(att_src + e*C1);
    const float4* ad = reinterpret_cast<const float4*>(att_dst + e*C1);

    float4 a = hs[l], b = as[l];
    float ps = a.x*b.x + a.y*b.y + a.z*b.z + a.w*b.w;
    float4 c = hd[l], d = ad[l];
    float pd = c.x*d.x + c.y*d.y + c.z*d.z + c.w*d.w;
    ps += __shfl_xor_sync(0xffffffffu, ps, 1);
    ps += __shfl_xor_sync(0xffffffffu, ps, 2);
    pd += __shfl_xor_sync(0xffffffffu, pd, 1);
    pd += __shfl_xor_sync(0xffffffffu, pd, 2);
    if ((l & 3) == 0) {
        g_asrc1[(e*NN + n)*H1 + (l >> 2)] = ps;
        g_adst1[(e*NN + n)*H1 + (l >> 2)] = pd;
    }
}

// ---------------------------------------------------------------------------
// Aggregation layer 1: one 128-thread block per (node, relation).
// Online segment softmax (== segment_max / exp / segment_sum), then
// coalesced gather-accumulate of source rows. relu on output.
// ---------------------------------------------------------------------------
__global__ void k_agg1() {
    int e = blockIdx.y, n = blockIdx.x;
    int c = threadIdx.x;          // channel 0..127
    int h = c >> 4;
    int off = g_offsets[e*(NN+1) + n];
    int deg = g_offsets[e*(NN+1) + n + 1] - off;
    float* out = g_out1 + (long)(e*NN + n) * C1;
    if (deg == 0) { out[c] = 0.f; return; }

    const int*   sr  = g_srcs + e*NE + off;
    const float* asr = g_asrc1 + e*NN*H1;
    float ad = g_adst1[(e*NN + n)*H1 + h];

    float m = -1e30f, s = 0.f;
    for (int i = 0; i < deg; i++) {
        int r = sr[i];
        float a = asr[r*H1 + h] + ad;
        a = a > 0.f ? a : 0.2f * a;
        if (a > m) { s = s * expf(m - a) + 1.f; m = a; }
        else        s += expf(a - m);
    }
    float inv = 1.f / (s + 1e-16f);
    const float* hsrc = g_h1 + c_SRC[e]*NN*C1;
    float accv = 0.f;
    for (int i = 0; i < deg; i++) {
        int r = sr[i];
        float a = asr[r*H1 + h] + ad;
        a = a > 0.f ? a : 0.2f * a;
        accv += expf(a - m) * inv * hsrc[r*C1 + c];
    }
    out[c] = fmaxf(accv, 0.f);
}

// ---------------------------------------------------------------------------
// Semantic score + group softmax (tiny)
// ---------------------------------------------------------------------------
__global__ void k_score1(const float* __restrict__ q) {
    __shared__ float red[128];
    __shared__ float sc[NR];
    int t = threadIdx.x;
    for (int e = 0; e < NR; e++) {
        float p = q[t] * g_colsum1[e*C1 + t];
        red[t] = p; __syncthreads();
        for (int s = 64; s > 0; s >>= 1) {
            if (t < s) red[t] += red[t + s];
            __syncthreads();
        }
        if (t == 0) sc[e] = red[0] / (float)NN;
        __syncthreads();
    }
    if (t < NT) {
        int b = c_GRPOFF[t], e2 = c_GRPOFF[t+1];
        float m = -1e30f;
        for (int g = b; g < e2; g++) m = fmaxf(m, sc[c_GRP[g]]);
        float ssum = 0.f;
        for (int g = b; g < e2; g++) ssum += expf(sc[c_GRP[g]] - m);
        for (int g = b; g < e2; g++)
            g_sattn1[c_GRP[g]] = expf(sc[c_GRP[g]] - m) / ssum;
    }
}

__global__ void k_score2(const float* __restrict__ q) {
    __shared__ float red[128];
    __shared__ float sc[NR];
    int t = threadIdx.x;
    for (int e = 0; e < NR; e++) {
        float p = (t < C2) ? q[t] * g_colsum2[e*C2 + t] : 0.f;
        red[t] = p; __syncthreads();
        for (int s = 64; s > 0; s >>= 1) {
            if (t < s) red[t] += red[t + s];
            __syncthreads();
        }
        if (t == 0) sc[e] = red[0] / (float)NN;
        __syncthreads();
    }
    if (t < NT) {
        int b = c_GRPOFF[t], e2 = c_GRPOFF[t+1];
        float m = -1e30f;
        for (int g = b; g < e2; g++) m = fmaxf(m, sc[c_GRP[g]]);
        float ssum = 0.f;
        for (int g = b; g < e2; g++) ssum += expf(sc[c_GRP[g]] - m);
        for (int g = b; g < e2; g++)
            g_sattn2[c_GRP[g]] = expf(sc[c_GRP[g]] - m) / ssum;
    }
}

// ---------------------------------------------------------------------------
// Fuse relations per dst type (layer1) + elu -> x2
// ---------------------------------------------------------------------------
__global__ void k_combine1() {
    long idx = (long)blockIdx.x * blockDim.x + threadIdx.x;
    if (idx >= (long)NT*NN*C1) return;
    int t  = (int)(idx / (NN*C1));
    int nc = (int)(idx - (long)t*NN*C1);
    float v = 0.f;
    for (int g = c_GRPOFF[t]; g < c_GRPOFF[t+1]; g++) {
        int e = c_GRP[g];
        v += g_sattn1[e] * g_out1[(long)e*NN*C1 + nc];
    }
    g_x2[idx] = v > 0.f ? v : expf(v) - 1.f;
}

// ---------------------------------------------------------------------------
// Layer 2 logits (H=1): warp per (relation, node)
// ---------------------------------------------------------------------------
__global__ void k_logits2(const float* __restrict__ att_src,
                          const float* __restrict__ att_dst)
{
    int e = blockIdx.y;
    int n = blockIdx.x * 8 + (threadIdx.x >> 5);
    if (n >= NN) return;
    int l = threadIdx.x & 31;
    float ps = g_h2[c_SRC[e]*NN*C2 + n*C2 + l] * att_src[e*C2 + l];
    float pd = g_h2[c_DST[e]*NN*C2 + n*C2 + l] * att_dst[e*C2 + l];
#pragma unroll
    for (int o = 16; o > 0; o >>= 1) {
        ps += __shfl_xor_sync(0xffffffffu, ps, o);
        pd += __shfl_xor_sync(0xffffffffu, pd, o);
    }
    if (l == 0) { g_asrc2[e*NN + n] = ps; g_adst2[e*NN + n] = pd; }
}

// ---------------------------------------------------------------------------
// Aggregation layer 2: warp per (node, relation), 4 nodes per block
// ---------------------------------------------------------------------------
__global__ void k_agg2() {
    int e = blockIdx.y;
    int n = blockIdx.x * 4 + (threadIdx.x >> 5);
    if (n >= NN) return;
    int c = threadIdx.x & 31;
    int off = g_offsets[e*(NN+1) + n];
    int deg = g_offsets[e*(NN+1) + n + 1] - off;
    float* out = g_out2 + (long)(e*NN + n) * C2;
    if (deg == 0) { out[c] = 0.f; return; }

    const int*   sr  = g_srcs + e*NE + off;
    const float* asr = g_asrc2 + e*NN;
    float ad = g_adst2[e*NN + n];

    float m = -1e30f, s = 0.f;
    for (int i = 0; i < deg; i++) {
        float a = asr[sr[i]] + ad;
        a = a > 0.f ? a : 0.2f * a;
        if (a > m) { s = s * expf(m - a) + 1.f; m = a; }
        else        s += expf(a - m);
    }
    float inv = 1.f / (s + 1e-16f);
    const float* hsrc = g_h2 + c_SRC[e]*NN*C2;
    float accv = 0.f;
    for (int i = 0; i < deg; i++) {
        int r = sr[i];
        float a = asr[r] + ad;
        a = a > 0.f ? a : 0.2f * a;
        accv += expf(a - m) * inv * hsrc[r*C2 + c];
    }
    out[c] = fmaxf(accv, 0.f);
}

// ---------------------------------------------------------------------------
// Fuse relations layer 2 + final per-node channel softmax -> d_out
// ---------------------------------------------------------------------------
__global__ void k_combine2(float* __restrict__ out) {
    int g = blockIdx.x * 8 + (threadIdx.x >> 5);
    if (g >= NT*NN) return;
    int t = g / NN, n = g - t*NN;
    int c = threadIdx.x & 31;
    float v = 0.f;
    for (int gi = c_GRPOFF[t]; gi < c_GRPOFF[t+1]; gi++) {
        int e = c_GRP[gi];
        v += g_sattn2[e] * g_out2[(long)(e*NN + n)*C2 + c];
    }
    float m = v;
#pragma unroll
    for (int o = 16; o > 0; o >>= 1)
        m = fmaxf(m, __shfl_xor_sync(0xffffffffu, m, o));
    float ex = expf(v - m);
    float s = ex;
#pragma unroll
    for (int o = 16; o > 0; o >>= 1)
        s += __shfl_xor_sync(0xffffffffu, s, o);
    out[(long)g*C2 + c] = ex / s;
}

// ---------------------------------------------------------------------------
// Host launcher
// ---------------------------------------------------------------------------
extern "C" void kernel_launch(void* const* d_in, const int* in_sizes, int n_in,
                              void* d_out, int out_size)
{
    const float* x[4] = {(const float*)d_in[0], (const float*)d_in[1],
                         (const float*)d_in[2], (const float*)d_in[3]};
    const int*   edges    = (const int*)  d_in[4];
    const float* proj1_W  = (const float*)d_in[5];
    const float* proj1_b  = (const float*)d_in[6];
    const float* att1_src = (const float*)d_in[7];
    const float* att1_dst = (const float*)d_in[8];
    const float* k1_W     = (const float*)d_in[9];
    const float* k1_b     = (const float*)d_in[10];
    const float* q1       = (const float*)d_in[11];
    const float* proj2_W  = (const float*)d_in[12];
    const float* proj2_b  = (const float*)d_in[13];
    const float* att2_src = (const float*)d_in[14];
    const float* att2_dst = (const float*)d_in[15];
    const float* k2_W     = (const float*)d_in[16];
    const float* k2_b     = (const float*)d_in[17];
    const float* q2       = (const float*)d_in[18];
    float* out = (float*)d_out;

    float *h1p, *x2p, *h2p, *out1p, *out2p, *cs1p, *cs2p;
    cudaGetSymbolAddress((void**)&h1p,   g_h1);
    cudaGetSymbolAddress((void**)&x2p,   g_x2);
    cudaGetSymbolAddress((void**)&h2p,   g_h2);
    cudaGetSymbolAddress((void**)&out1p, g_out1);
    cudaGetSymbolAddress((void**)&out2p, g_out2);
    cudaGetSymbolAddress((void**)&cs1p,  g_colsum1);
    cudaGetSymbolAddress((void**)&cs2p,  g_colsum2);

    const int MT = (NN + 127) / 128;   // 235 row tiles

    // zero counts/colsums, build CSR (shared by both layers)
    k_zero <<<(NR*NN + 255)/256, 256>>>();
    k_count<<<(NR*NE + 255)/256, 256>>>(edges);
    k_scan <<<NR, 1024>>>();
    k_fill <<<(NR*NE + 255)/256, 256>>>(edges);

    // ---- layer 1 ----
    for (int t = 0; t < NT; t++)
        k_gemm<0><<<dim3(MT, 1, 1), 256>>>(
            x[t], proj1_W + (long)t*IN1*C1, proj1_b + t*C1,
            h1p + (long)t*NN*C1, NN, C1, IN1, 0, 0, nullptr, 0);

    k_logits1<<<dim3((NN + 7)/8, NR), 256>>>(att1_src, att1_dst);
    k_agg1   <<<dim3(NN, NR), 128>>>();

    k_gemm<1><<<dim3(MT, 1, NR), 256>>>(
        out1p, k1_W, k1_b, nullptr, NN, C1, C1,
        (long)NN*C1, 0, cs1p, C1);
    k_score1<<<1, 128>>>(q1);
    k_combine1<<<((long)NT*NN*C1 + 255)/256, 256>>>();

    // ---- layer 2 ----
    for (int t = 0; t < NT; t++)
        k_gemm<0><<<dim3(MT, 1, 1), 256>>>(
            x2p + (long)t*NN*C1, proj2_W + (long)t*C1*C2, proj2_b + t*C2,
            h2p + (long)t*NN*C2, NN, C2, C1, 0, 0, nullptr, 0);

    k_logits2<<<dim3((NN + 7)/8, NR), 256>>>(att2_src, att2_dst);
    k_agg2   <<<dim3((NN + 3)/4, NR), 128>>>();

    k_gemm<1><<<dim3(MT, 1, NR), 256>>>(
        out2p, k2_W, k2_b, nullptr, NN, C2, C2,
        (long)NN*C2, 0, cs2p, C2);
    k_score2<<<1, 128>>>(q2);

    k_combine2<<<(NT*NN + 7)/8, 256>>>(out);
}

// round 2
// speedup vs baseline: 1.0009x; 1.0009x over previous
#include <cuda_runtime.h>
#include <math.h>

// ---------------------------------------------------------------------------
// Problem constants
// ---------------------------------------------------------------------------
constexpr int NN  = 30000;    // nodes per type
constexpr int NE  = 400000;   // edges per relation
constexpr int NR  = 10;       // relations
constexpr int NT  = 4;        // node types
constexpr int C1  = 128;      // layer1 channels
constexpr int H1  = 8;        // layer1 heads
constexpr int IN1 = 256;      // layer1 input dim
constexpr int C2  = 32;       // layer2 channels

__constant__ int c_SRC[NR]    = {0,1,2,3,0,1,2,1,3,1};
__constant__ int c_DST[NR]    = {0,1,2,3,1,0,1,2,1,3};
__constant__ int c_GRPOFF[5]  = {0,2,6,8,10};
__constant__ int c_GRP[NR]    = {0,5, 1,4,6,8, 2,7, 3,9};

// ---------------------------------------------------------------------------
// Scratch (static device arrays: allocation-free)
// ---------------------------------------------------------------------------
__device__ float g_h1   [NT*NN*C1];     // projected features, layer 1
__device__ float g_asrc1[NR*NN*H1];
__device__ float g_adst1[NR*NN*H1];
__device__ float g_out1 [NR*NN*C1];     // relu(agg) per relation, layer 1
__device__ float g_x2   [NT*NN*C1];     // elu(fused) -> layer2 input
__device__ float g_h2   [NT*NN*C2];
__device__ float g_asrc2[NR*NN];
__device__ float g_adst2[NR*NN];
__device__ float g_out2 [NR*NN*C2];
__device__ float g_colsum1[NR*C1];
__device__ float g_colsum2[NR*C2];
__device__ float g_sattn1[NR];
__device__ float g_sattn2[NR];
__device__ int   g_counts [NR*NN];
__device__ int   g_offsets[NR*(NN+1)];
__device__ int   g_cursor [NR*NN];
__device__ int   g_srcs   [NR*NE];

// ---------------------------------------------------------------------------
// Zeroing (counts + colsums); graph-capturable, no memset API needed
// ---------------------------------------------------------------------------
__global__ void k_zero() {
    int i = blockIdx.x * blockDim.x + threadIdx.x;
    if (i < NR*NN) g_counts[i] = 0;
    if (i < NR*C1) g_colsum1[i] = 0.f;
    if (i < NR*C2) g_colsum2[i] = 0.f;
}

// ---------------------------------------------------------------------------
// CSR build by destination (shared by both layers)
// ---------------------------------------------------------------------------
__global__ void k_count(const int* __restrict__ edges) {
    int idx = blockIdx.x * blockDim.x + threadIdx.x;
    if (idx >= NR*NE) return;
    int e = idx / NE, i = idx - e*NE;
    int col = edges[e*2*NE + NE + i];
    atomicAdd(&g_counts[e*NN + col], 1);
}

__global__ void k_scan() {   // one block (1024 threads) per relation
    const int e = blockIdx.x;
    const int t = threadIdx.x;
    constexpr int CH = 30;   // 1024*30 = 30720 >= 30000
    int base = t * CH;
    int cnt[CH];
    int sum = 0;
#pragma unroll
    for (int i = 0; i < CH; i++) {
        int idx = base + i;
        int v = (idx < NN) ? g_counts[e*NN + idx] : 0;
        cnt[i] = v; sum += v;
    }
    __shared__ int s[1024];
    s[t] = sum; __syncthreads();
    for (int d = 1; d < 1024; d <<= 1) {
        int v = (t >= d) ? s[t-d] : 0;
        __syncthreads();
        s[t] += v;
        __syncthreads();
    }
    int run = s[t] - sum;   // exclusive prefix
#pragma unroll
    for (int i = 0; i < CH; i++) {
        int idx = base + i;
        if (idx < NN) {
            g_offsets[e*(NN+1) + idx] = run;
            g_cursor [e*NN + idx]     = run;
            run += cnt[i];
        }
    }
    if (t == 1023) g_offsets[e*(NN+1) + NN] = s[1023];
}

__global__ void k_fill(const int* __restrict__ edges) {
    int idx = blockIdx.x * blockDim.x + threadIdx.x;
    if (idx >= NR*NE) return;
    int e = idx / NE, i = idx - e*NE;
    int row = edges[e*2*NE + i];
    int col = edges[e*2*NE + NE + i];
    int pos = atomicAdd(&g_cursor[e*NN + col], 1);
    g_srcs[e*NE + pos] = row;
}

// ---------------------------------------------------------------------------
// Generic fp32 GEMM: C[MxN] = A[MxK] @ B[KxN] (+bias).
// MODE 0: store C + bias.  MODE 1: accumulate column sums of tanh(C+bias)
// into colsum (semantic-attention score path, no C store).
// BM=BN=128, BK=16, 256 threads, 8x8 microtile.
// ---------------------------------------------------------------------------
template <int MODE>
__global__ void __launch_bounds__(256)
k_gemm(const float* __restrict__ A, const float* __restrict__ B,
       const float* __restrict__ bias, float* __restrict__ C,
       int M, int Ncols, int K, long strideA, long strideC,
       float* __restrict__ colsum, int colsumStride)
{
    constexpr int BM = 128, BN = 128, BK = 16;
    __shared__ float As[BK][BM];
    __shared__ float Bs[BK][BN];

    const int z = blockIdx.z;
    A += (long)z * strideA;
    if (MODE == 0) C += (long)z * strideC;

    const int m0 = blockIdx.x * BM;
    const int n0 = blockIdx.y * BN;
    const int tid = threadIdx.x;
    const int tx = tid & 15, ty = tid >> 4;

    float acc[8][8];
#pragma unroll
    for (int i = 0; i < 8; i++)
#pragma unroll
        for (int j = 0; j < 8; j++) acc[i][j] = 0.f;

    for (int k0 = 0; k0 < K; k0 += BK) {
        // load A tile (transposed into As[k][m])
#pragma unroll
        for (int it = 0; it < 2; it++) {
            int lin = tid + it * 256;
            int m = lin >> 2, kq = lin & 3;
            float4 v = {0.f, 0.f, 0.f, 0.f};
            if (m0 + m < M)
                v = *reinterpret_cast<const float4*>(A + (long)(m0+m)*K + k0 + kq*4);
            As[kq*4+0][m] = v.x; As[kq*4+1][m] = v.y;
            As[kq*4+2][m] = v.z; As[kq*4+3][m] = v.w;
        }
        // load B tile
#pragma unroll
        for (int it = 0; it < 2; it++) {
            int lin = tid + it * 256;
            int k = lin >> 5, nq = lin & 31;
            float4 v = {0.f, 0.f, 0.f, 0.f};
            if (n0 + nq*4 + 3 < Ncols)
                v = *reinterpret_cast<const float4*>(B + (long)(k0+k)*Ncols + n0 + nq*4);
            *reinterpret_cast<float4*>(&Bs[k][nq*4]) = v;
        }
        __syncthreads();
#pragma unroll
        for (int k = 0; k < BK; k++) {
            float a[8], b[8];
#pragma unroll
            for (int i = 0; i < 8; i++) a[i] = As[k][ty*8 + i];
#pragma unroll
            for (int j = 0; j < 8; j++) b[j] = Bs[k][tx*8 + j];
#pragma unroll
            for (int i = 0; i < 8; i++)
#pragma unroll
                for (int j = 0; j < 8; j++) acc[i][j] += a[i] * b[j];
        }
        __syncthreads();
    }

    if (MODE == 0) {
#pragma unroll
        for (int i = 0; i < 8; i++) {
            int r = m0 + ty*8 + i;
            if (r >= M) continue;
#pragma unroll
            for (int j = 0; j < 8; j++) {
                int c = n0 + tx*8 + j;
                if (c < Ncols) C[(long)r*Ncols + c] = acc[i][j] + bias[c];
            }
        }
    } else {
        __shared__ float cs[BN];
        if (tid < BN) cs[tid] = 0.f;
        __syncthreads();
#pragma unroll
        for (int j = 0; j < 8; j++) {
            int c = n0 + tx*8 + j;
            if (c < Ncols) {
                float bb = bias[c];
                float p = 0.f;
#pragma unroll
                for (int i = 0; i < 8; i++) {
                    int r = m0 + ty*8 + i;
                    if (r < M) p += tanhf(acc[i][j] + bb);
                }
                atomicAdd(&cs[tx*8 + j], p);
            }
        }
        __syncthreads();
        if (tid < BN && n0 + tid < Ncols)
            atomicAdd(&colsum[z*colsumStride + n0 + tid], cs[tid]);
    }
}

// ---------------------------------------------------------------------------
// Attention logits, layer 1: warp per (relation, node)
// ---------------------------------------------------------------------------
__global__ void k_logits1(const float* __restrict__ att_src,
                          const float* __restrict__ att_dst)
{
    int e = blockIdx.y;
    int n = blockIdx.x * 8 + (threadIdx.x >> 5);
    if (n >= NN) return;
    int l = threadIdx.x & 31;

    const float4* hs = reinterpret_cast<const float4*>(g_h1 + c_SRC[e]*NN*C1 + n*C1);
    const float4* hd = reinterpret_cast<const float4*>(g_h1 + c_DST[e]*NN*C1 + n*C1);
    const float4* as = reinterpret_cast<const float4*>(att_src + e*C1);
    const float4* ad = reinterpret_cast<const float4*>(att_dst + e*C1);

    float4 a = hs[l], b = as[l];
    float ps = a.x*b.x + a.y*b.y + a.z*b.z + a.w*b.w;
    float4 c = hd[l], d = ad[l];
    float pd = c.x*d.x + c.y*d.y + c.z*d.z + c.w*d.w;
    ps += __shfl_xor_sync(0xffffffffu, ps, 1);
    ps += __shfl_xor_sync(0xffffffffu, ps, 2);
    pd += __shfl_xor_sync(0xffffffffu, pd, 1);
    pd += __shfl_xor_sync(0xffffffffu, pd, 2);
    if ((l & 3) == 0) {
        g_asrc1[(e*NN + n)*H1 + (l >> 2)] = ps;
        g_adst1[(e*NN + n)*H1 + (l >> 2)] = pd;
    }
}

// ---------------------------------------------------------------------------
// Aggregation layer 1: one 128-thread block per (node, relation).
// Online segment softmax (== segment_max / exp / segment_sum), then
// coalesced gather-accumulate of source rows. relu on output.
// ---------------------------------------------------------------------------
__global__ void k_agg1() {
    int e = blockIdx.y, n = blockIdx.x;
    int c = threadIdx.x;          // channel 0..127
    int h = c >> 4;
    int off = g_offsets[e*(NN+1) + n];
    int deg = g_offsets[e*(NN+1) + n + 1] - off;
    float* out = g_out1 + (long)(e*NN + n) * C1;
    if (deg == 0) { out[c] = 0.f; return; }

    const int*   sr  = g_srcs + e*NE + off;
    const float* asr = g_asrc1 + e*NN*H1;
    float ad = g_adst1[(e*NN + n)*H1 + h];

    float m = -1e30f, s = 0.f;
    for (int i = 0; i < deg; i++) {
        int r = sr[i];
        float a = asr[r*H1 + h] + ad;
        a = a > 0.f ? a : 0.2f * a;
        if (a > m) { s = s * expf(m - a) + 1.f; m = a; }
        else        s += expf(a - m);
    }
    float inv = 1.f / (s + 1e-16f);
    const float* hsrc = g_h1 + c_SRC[e]*NN*C1;
    float accv = 0.f;
    for (int i = 0; i < deg; i++) {
        int r = sr[i];
        float a = asr[r*H1 + h] + ad;
        a = a > 0.f ? a : 0.2f * a;
        accv += expf(a - m) * inv * hsrc[r*C1 + c];
    }
    out[c] = fmaxf(accv, 0.f);
}

// ---------------------------------------------------------------------------
// Semantic score + group softmax (tiny)
// ---------------------------------------------------------------------------
__global__ void k_score1(const float* __restrict__ q) {
    __shared__ float red[128];
    __shared__ float sc[NR];
    int t = threadIdx.x;
    for (int e = 0; e < NR; e++) {
        float p = q[t] * g_colsum1[e*C1 + t];
        red[t] = p; __syncthreads();
        for (int s = 64; s > 0; s >>= 1) {
            if (t < s) red[t] += red[t + s];
            __syncthreads();
        }
        if (t == 0) sc[e] = red[0] / (float)NN;
        __syncthreads();
    }
    if (t < NT) {
        int b = c_GRPOFF[t], e2 = c_GRPOFF[t+1];
        float m = -1e30f;
        for (int g = b; g < e2; g++) m = fmaxf(m, sc[c_GRP[g]]);
        float ssum = 0.f;
        for (int g = b; g < e2; g++) ssum += expf(sc[c_GRP[g]] - m);
        for (int g = b; g < e2; g++)
            g_sattn1[c_GRP[g]] = expf(sc[c_GRP[g]] - m) / ssum;
    }
}

__global__ void k_score2(const float* __restrict__ q) {
    __shared__ float red[128];
    __shared__ float sc[NR];
    int t = threadIdx.x;
    for (int e = 0; e < NR; e++) {
        float p = (t < C2) ? q[t] * g_colsum2[e*C2 + t] : 0.f;
        red[t] = p; __syncthreads();
        for (int s = 64; s > 0; s >>= 1) {
            if (t < s) red[t] += red[t + s];
            __syncthreads();
        }
        if (t == 0) sc[e] = red[0] / (float)NN;
        __syncthreads();
    }
    if (t < NT) {
        int b = c_GRPOFF[t], e2 = c_GRPOFF[t+1];
        float m = -1e30f;
        for (int g = b; g < e2; g++) m = fmaxf(m, sc[c_GRP[g]]);
        float ssum = 0.f;
        for (int g = b; g < e2; g++) ssum += expf(sc[c_GRP[g]] - m);
        for (int g = b; g < e2; g++)
            g_sattn2[c_GRP[g]] = expf(sc[c_GRP[g]] - m) / ssum;
    }
}

// ---------------------------------------------------------------------------
// Fuse relations per dst type (layer1) + elu -> x2
// ---------------------------------------------------------------------------
__global__ void k_combine1() {
    long idx = (long)blockIdx.x * blockDim.x + threadIdx.x;
    if (idx >= (long)NT*NN*C1) return;
    int t  = (int)(idx / (NN*C1));
    int nc = (int)(idx - (long)t*NN*C1);
    float v = 0.f;
    for (int g = c_GRPOFF[t]; g < c_GRPOFF[t+1]; g++) {
        int e = c_GRP[g];
        v += g_sattn1[e] * g_out1[(long)e*NN*C1 + nc];
    }
    g_x2[idx] = v > 0.f ? v : expf(v) - 1.f;
}

// ---------------------------------------------------------------------------
// Layer 2 logits (H=1): warp per (relation, node)
// ---------------------------------------------------------------------------
__global__ void k_logits2(const float* __restrict__ att_src,
                          const float* __restrict__ att_dst)
{
    int e = blockIdx.y;
    int n = blockIdx.x * 8 + (threadIdx.x >> 5);
    if (n >= NN) return;
    int l = threadIdx.x & 31;
    float ps = g_h2[c_SRC[e]*NN*C2 + n*C2 + l] * att_src[e*C2 + l];
    float pd = g_h2[c_DST[e]*NN*C2 + n*C2 + l] * att_dst[e*C2 + l];
#pragma unroll
    for (int o = 16; o > 0; o >>= 1) {
        ps += __shfl_xor_sync(0xffffffffu, ps, o);
        pd += __shfl_xor_sync(0xffffffffu, pd, o);
    }
    if (l == 0) { g_asrc2[e*NN + n] = ps; g_adst2[e*NN + n] = pd; }
}

// ---------------------------------------------------------------------------
// Aggregation layer 2: warp per (node, relation), 4 nodes per block
// ---------------------------------------------------------------------------
__global__ void k_agg2() {
    int e = blockIdx.y;
    int n = blockIdx.x * 4 + (threadIdx.x >> 5);
    if (n >= NN) return;
    int c = threadIdx.x & 31;
    int off = g_offsets[e*(NN+1) + n];
    int deg = g_offsets[e*(NN+1) + n + 1] - off;
    float* out = g_out2 + (long)(e*NN + n) * C2;
    if (deg == 0) { out[c] = 0.f; return; }

    const int*   sr  = g_srcs + e*NE + off;
    const float* asr = g_asrc2 + e*NN;
    float ad = g_adst2[e*NN + n];

    float m = -1e30f, s = 0.f;
    for (int i = 0; i < deg; i++) {
        float a = asr[sr[i]] + ad;
        a = a > 0.f ? a : 0.2f * a;
        if (a > m) { s = s * expf(m - a) + 1.f; m = a; }
        else        s += expf(a - m);
    }
    float inv = 1.f / (s + 1e-16f);
    const float* hsrc = g_h2 + c_SRC[e]*NN*C2;
    float accv = 0.f;
    for (int i = 0; i < deg; i++) {
        int r = sr[i];
        float a = asr[r] + ad;
        a = a > 0.f ? a : 0.2f * a;
        accv += expf(a - m) * inv * hsrc[r*C2 + c];
    }
    out[c] = fmaxf(accv, 0.f);
}

// ---------------------------------------------------------------------------
// Fuse relations layer 2 + final per-node channel softmax -> d_out
// ---------------------------------------------------------------------------
__global__ void k_combine2(float* __restrict__ out) {
    int g = blockIdx.x * 8 + (threadIdx.x >> 5);
    if (g >= NT*NN) return;
    int t = g / NN, n = g - t*NN;
    int c = threadIdx.x & 31;
    float v = 0.f;
    for (int gi = c_GRPOFF[t]; gi < c_GRPOFF[t+1]; gi++) {
        int e = c_GRP[gi];
        v += g_sattn2[e] * g_out2[(long)(e*NN + n)*C2 + c];
    }
    float m = v;
#pragma unroll
    for (int o = 16; o > 0; o >>= 1)
        m = fmaxf(m, __shfl_xor_sync(0xffffffffu, m, o));
    float ex = expf(v - m);
    float s = ex;
#pragma unroll
    for (int o = 16; o > 0; o >>= 1)
        s += __shfl_xor_sync(0xffffffffu, s, o);
    out[(long)g*C2 + c] = ex / s;
}

// ---------------------------------------------------------------------------
// Host launcher
// ---------------------------------------------------------------------------
extern "C" void kernel_launch(void* const* d_in, const int* in_sizes, int n_in,
                              void* d_out, int out_size)
{
    const float* x[4] = {(const float*)d_in[0], (const float*)d_in[1],
                         (const float*)d_in[2], (const float*)d_in[3]};
    const int*   edges    = (const int*)  d_in[4];
    const float* proj1_W  = (const float*)d_in[5];
    const float* proj1_b  = (const float*)d_in[6];
    const float* att1_src = (const float*)d_in[7];
    const float* att1_dst = (const float*)d_in[8];
    const float* k1_W     = (const float*)d_in[9];
    const float* k1_b     = (const float*)d_in[10];
    const float* q1       = (const float*)d_in[11];
    const float* proj2_W  = (const float*)d_in[12];
    const float* proj2_b  = (const float*)d_in[13];
    const float* att2_src = (const float*)d_in[14];
    const float* att2_dst = (const float*)d_in[15];
    const float* k2_W     = (const float*)d_in[16];
    const float* k2_b     = (const float*)d_in[17];
    const float* q2       = (const float*)d_in[18];
    float* out = (float*)d_out;

    float *h1p, *x2p, *h2p, *out1p, *out2p, *cs1p, *cs2p;
    cudaGetSymbolAddress((void**)&h1p,   g_h1);
    cudaGetSymbolAddress((void**)&x2p,   g_x2);
    cudaGetSymbolAddress((void**)&h2p,   g_h2);
    cudaGetSymbolAddress((void**)&out1p, g_out1);
    cudaGetSymbolAddress((void**)&out2p, g_out2);
    cudaGetSymbolAddress((void**)&cs1p,  g_colsum1);
    cudaGetSymbolAddress((void**)&cs2p,  g_colsum2);

    const int MT = (NN + 127) / 128;   // 235 row tiles

    // zero counts/colsums, build CSR (shared by both layers)
    k_zero <<<(NR*NN + 255)/256, 256>>>();
    k_count<<<(NR*NE + 255)/256, 256>>>(edges);
    k_scan <<<NR, 1024>>>();
    k_fill <<<(NR*NE + 255)/256, 256>>>(edges);

    // ---- layer 1 ----
    for (int t = 0; t < NT; t++)
        k_gemm<0><<<dim3(MT, 1, 1), 256>>>(
            x[t], proj1_W + (long)t*IN1*C1, proj1_b + t*C1,
            h1p + (long)t*NN*C1, NN, C1, IN1, 0, 0, nullptr, 0);

    k_logits1<<<dim3((NN + 7)/8, NR), 256>>>(att1_src, att1_dst);
    k_agg1   <<<dim3(NN, NR), 128>>>();

    k_gemm<1><<<dim3(MT, 1, NR), 256>>>(
        out1p, k1_W, k1_b, nullptr, NN, C1, C1,
        (long)NN*C1, 0, cs1p, C1);
    k_score1<<<1, 128>>>(q1);
    k_combine1<<<((long)NT*NN*C1 + 255)/256, 256>>>();

    // ---- layer 2 ----
    for (int t = 0; t < NT; t++)
        k_gemm<0><<<dim3(MT, 1, 1), 256>>>(
            x2p + (long)t*NN*C1, proj2_W + (long)t*C1*C2, proj2_b + t*C2,
            h2p + (long)t*NN*C2, NN, C2, C1, 0, 0, nullptr, 0);

    k_logits2<<<dim3((NN + 7)/8, NR), 256>>>(att2_src, att2_dst);
    k_agg2   <<<dim3((NN + 3)/4, NR), 128>>>();

    k_gemm<1><<<dim3(MT, 1, NR), 256>>>(
        out2p, k2_W, k2_b, nullptr, NN, C2, C2,
        (long)NN*C2, 0, cs2p, C2);
    k_score2<<<1, 128>>>(q2);

    k_combine2<<<(NT*NN + 7)/8, 256>>>(out);
}

// round 3
// speedup vs baseline: 1.2875x; 1.2864x over previous
#include <cuda_runtime.h>
#include <math.h>

// ---------------------------------------------------------------------------
// Problem constants
// ---------------------------------------------------------------------------
constexpr int NN  = 30000;    // nodes per type
constexpr int NE  = 400000;   // edges per relation
constexpr int NR  = 10;       // relations
constexpr int NT  = 4;        // node types
constexpr int C1  = 128;      // layer1 channels
constexpr int H1  = 8;        // layer1 heads
constexpr int IN1 = 256;      // layer1 input dim
constexpr int C2  = 32;       // layer2 channels

__constant__ int c_SRC[NR]    = {0,1,2,3,0,1,2,1,3,1};
__constant__ int c_DST[NR]    = {0,1,2,3,1,0,1,2,1,3};
__constant__ int c_GRPOFF[5]  = {0,2,6,8,10};
__constant__ int c_GRP[NR]    = {0,5, 1,4,6,8, 2,7, 3,9};

// ---------------------------------------------------------------------------
// Scratch (static device arrays: allocation-free)
// ---------------------------------------------------------------------------
__device__ float g_h1   [NT*NN*C1];     // projected features, layer 1
__device__ float g_asrc1[NR*NN*H1];
__device__ float g_adst1[NR*NN*H1];
__device__ float g_out1 [NR*NN*C1];     // relu(agg) per relation, layer 1
__device__ float g_x2   [NT*NN*C1];     // elu(fused) -> layer2 input
__device__ float g_h2   [NT*NN*C2];
__device__ float g_asrc2[NR*NN];
__device__ float g_adst2[NR*NN];
__device__ float g_out2 [NR*NN*C2];
__device__ float g_colsum1[NR*C1];
__device__ float g_colsum2[NR*C2];
__device__ float g_sattn1[NR];
__device__ float g_sattn2[NR];
__device__ int   g_counts [NR*NN];
__device__ int   g_offsets[NR*(NN+1)];
__device__ int   g_cursor [NR*NN];
__device__ int   g_srcs   [NR*NE];
__device__ float g_w1     [(long)NR*NE*H1];  // normalized edge weights, layer 1
__device__ float g_w2     [NR*NE];           // normalized edge weights, layer 2

// ---------------------------------------------------------------------------
// Zeroing (counts + colsums)
// ---------------------------------------------------------------------------
__global__ void k_zero() {
    int i = blockIdx.x * blockDim.x + threadIdx.x;
    if (i < NR*NN) g_counts[i] = 0;
    if (i < NR*C1) g_colsum1[i] = 0.f;
    if (i < NR*C2) g_colsum2[i] = 0.f;
}

// ---------------------------------------------------------------------------
// CSR build by destination (shared by both layers)
// ---------------------------------------------------------------------------
__global__ void k_count(const int* __restrict__ edges) {
    int idx = blockIdx.x * blockDim.x + threadIdx.x;
    if (idx >= NR*NE) return;
    int e = idx / NE, i = idx - e*NE;
    int col = edges[e*2*NE + NE + i];
    atomicAdd(&g_counts[e*NN + col], 1);
}

__global__ void k_scan() {   // one block (1024 threads) per relation
    const int e = blockIdx.x;
    const int t = threadIdx.x;
    constexpr int CH = 30;   // 1024*30 = 30720 >= 30000
    int base = t * CH;
    int cnt[CH];
    int sum = 0;
#pragma unroll
    for (int i = 0; i < CH; i++) {
        int idx = base + i;
        int v = (idx < NN) ? g_counts[e*NN + idx] : 0;
        cnt[i] = v; sum += v;
    }
    __shared__ int s[1024];
    s[t] = sum; __syncthreads();
    for (int d = 1; d < 1024; d <<= 1) {
        int v = (t >= d) ? s[t-d] : 0;
        __syncthreads();
        s[t] += v;
        __syncthreads();
    }
    int run = s[t] - sum;   // exclusive prefix
#pragma unroll
    for (int i = 0; i < CH; i++) {
        int idx = base + i;
        if (idx < NN) {
            g_offsets[e*(NN+1) + idx] = run;
            g_cursor [e*NN + idx]     = run;
            run += cnt[i];
        }
    }
    if (t == 1023) g_offsets[e*(NN+1) + NN] = s[1023];
}

__global__ void k_fill(const int* __restrict__ edges) {
    int idx = blockIdx.x * blockDim.x + threadIdx.x;
    if (idx >= NR*NE) return;
    int e = idx / NE, i = idx - e*NE;
    int row = edges[e*2*NE + i];
    int col = edges[e*2*NE + NE + i];
    int pos = atomicAdd(&g_cursor[e*NN + col], 1);
    g_srcs[e*NE + pos] = row;
}

// ---------------------------------------------------------------------------
// Generic fp32 GEMM: C[MxN] = A[MxK] @ B[KxN] (+bias).
// MODE 0: store C + bias.  MODE 1: accumulate column sums of tanh(C+bias)
// ---------------------------------------------------------------------------
template <int MODE>
__global__ void __launch_bounds__(256)
k_gemm(const float* __restrict__ A, const float* __restrict__ B,
       const float* __restrict__ bias, float* __restrict__ C,
       int M, int Ncols, int K, long strideA, long strideC,
       float* __restrict__ colsum, int colsumStride)
{
    constexpr int BM = 128, BN = 128, BK = 16;
    __shared__ float As[BK][BM];
    __shared__ float Bs[BK][BN];

    const int z = blockIdx.z;
    A += (long)z * strideA;
    if (MODE == 0) C += (long)z * strideC;

    const int m0 = blockIdx.x * BM;
    const int n0 = blockIdx.y * BN;
    const int tid = threadIdx.x;
    const int tx = tid & 15, ty = tid >> 4;

    float acc[8][8];
#pragma unroll
    for (int i = 0; i < 8; i++)
#pragma unroll
        for (int j = 0; j < 8; j++) acc[i][j] = 0.f;

    for (int k0 = 0; k0 < K; k0 += BK) {
#pragma unroll
        for (int it = 0; it < 2; it++) {
            int lin = tid + it * 256;
            int m = lin >> 2, kq = lin & 3;
            float4 v = {0.f, 0.f, 0.f, 0.f};
            if (m0 + m < M)
                v = *reinterpret_cast<const float4*>(A + (long)(m0+m)*K + k0 + kq*4);
            As[kq*4+0][m] = v.x; As[kq*4+1][m] = v.y;
            As[kq*4+2][m] = v.z; As[kq*4+3][m] = v.w;
        }
#pragma unroll
        for (int it = 0; it < 2; it++) {
            int lin = tid + it * 256;
            int k = lin >> 5, nq = lin & 31;
            float4 v = {0.f, 0.f, 0.f, 0.f};
            if (n0 + nq*4 + 3 < Ncols)
                v = *reinterpret_cast<const float4*>(B + (long)(k0+k)*Ncols + n0 + nq*4);
            *reinterpret_cast<float4*>(&Bs[k][nq*4]) = v;
        }
        __syncthreads();
#pragma unroll
        for (int k = 0; k < BK; k++) {
            float a[8], b[8];
#pragma unroll
            for (int i = 0; i < 8; i++) a[i] = As[k][ty*8 + i];
#pragma unroll
            for (int j = 0; j < 8; j++) b[j] = Bs[k][tx*8 + j];
#pragma unroll
            for (int i = 0; i < 8; i++)
#pragma unroll
                for (int j = 0; j < 8; j++) acc[i][j] += a[i] * b[j];
        }
        __syncthreads();
    }

    if (MODE == 0) {
#pragma unroll
        for (int i = 0; i < 8; i++) {
            int r = m0 + ty*8 + i;
            if (r >= M) continue;
#pragma unroll
            for (int j = 0; j < 8; j++) {
                int c = n0 + tx*8 + j;
                if (c < Ncols) C[(long)r*Ncols + c] = acc[i][j] + bias[c];
            }
        }
    } else {
        __shared__ float cs[BN];
        if (tid < BN) cs[tid] = 0.f;
        __syncthreads();
#pragma unroll
        for (int j = 0; j < 8; j++) {
            int c = n0 + tx*8 + j;
            if (c < Ncols) {
                float bb = bias[c];
                float p = 0.f;
#pragma unroll
                for (int i = 0; i < 8; i++) {
                    int r = m0 + ty*8 + i;
                    if (r < M) p += tanhf(acc[i][j] + bb);
                }
                atomicAdd(&cs[tx*8 + j], p);
            }
        }
        __syncthreads();
        if (tid < BN && n0 + tid < Ncols)
            atomicAdd(&colsum[z*colsumStride + n0 + tid], cs[tid]);
    }
}

// ---------------------------------------------------------------------------
// Attention logits, layer 1: warp per (relation, node)
// ---------------------------------------------------------------------------
__global__ void k_logits1(const float* __restrict__ att_src,
                          const float* __restrict__ att_dst)
{
    int e = blockIdx.y;
    int n = blockIdx.x * 8 + (threadIdx.x >> 5);
    if (n >= NN) return;
    int l = threadIdx.x & 31;

    const float4* hs = reinterpret_cast<const float4*>(g_h1 + c_SRC[e]*NN*C1 + n*C1);
    const float4* hd = reinterpret_cast<const float4*>(g_h1 + c_DST[e]*NN*C1 + n*C1);
    const float4* as = reinterpret_cast<const float4*>(att_src + e*C1);
    const float4* ad = reinterpret_cast<const float4*>(att_dst + e*C1);

    float4 a = hs[l], b = as[l];
    float ps = a.x*b.x + a.y*b.y + a.z*b.z + a.w*b.w;
    float4 c = hd[l], d = ad[l];
    float pd = c.x*d.x + c.y*d.y + c.z*d.z + c.w*d.w;
    ps += __shfl_xor_sync(0xffffffffu, ps, 1);
    ps += __shfl_xor_sync(0xffffffffu, ps, 2);
    pd += __shfl_xor_sync(0xffffffffu, pd, 1);
    pd += __shfl_xor_sync(0xffffffffu, pd, 2);
    if ((l & 3) == 0) {
        g_asrc1[(e*NN + n)*H1 + (l >> 2)] = ps;
        g_adst1[(e*NN + n)*H1 + (l >> 2)] = pd;
    }
}

// ---------------------------------------------------------------------------
// Segment softmax, layer 1: one warp per (relation, node).
// 8 heads x 4 lanes; lanes stride the edge list; online (m, s) merged via
// shfl within each 4-lane head group; normalized weights written CSR-ordered.
// One expf per (edge, head) instead of 16.
// ---------------------------------------------------------------------------
__global__ void k_soft1() {
    int e = blockIdx.y;
    int n = blockIdx.x * 8 + (threadIdx.x >> 5);
    if (n >= NN) return;
    int l  = threadIdx.x & 31;
    int h  = l >> 2;
    int il = l & 3;

    int off = g_offsets[e*(NN+1) + n];
    int deg = g_offsets[e*(NN+1) + n + 1] - off;
    if (deg == 0) return;

    const int*   sr  = g_srcs + e*NE + off;
    const float* asr = g_asrc1 + e*NN*H1;
    float ad = g_adst1[(e*NN + n)*H1 + h];

    float m = -1e30f, s = 0.f;
    for (int i = il; i < deg; i += 4) {
        float a = asr[sr[i]*H1 + h] + ad;
        a = a > 0.f ? a : 0.2f * a;
        if (a > m) { s = s * expf(m - a) + 1.f; m = a; }
        else        s += expf(a - m);
    }
    // merge (m,s) across the 4 lanes of this head group
#pragma unroll
    for (int o = 1; o <= 2; o <<= 1) {
        float mo = __shfl_xor_sync(0xffffffffu, m, o);
        float so = __shfl_xor_sync(0xffffffffu, s, o);
        float mn = fmaxf(m, mo);
        s = s * expf(m - mn) + so * expf(mo - mn);
        m = mn;
    }
    float inv = 1.f / (s + 1e-16f);
    float* w = g_w1 + (long)(e*NE + off) * H1;
    for (int i = il; i < deg; i += 4) {
        float a = asr[sr[i]*H1 + h] + ad;
        a = a > 0.f ? a : 0.2f * a;
        w[i*H1 + h] = expf(a - m) * inv;
    }
}

// ---------------------------------------------------------------------------
// Aggregation layer 1: pure weighted gather (no transcendentals).
// One 128-thread block per (node, relation).
// ---------------------------------------------------------------------------
__global__ void k_agg1() {
    int e = blockIdx.y, n = blockIdx.x;
    int c = threadIdx.x;          // channel 0..127
    int h = c >> 4;
    int off = g_offsets[e*(NN+1) + n];
    int deg = g_offsets[e*(NN+1) + n + 1] - off;
    float* out = g_out1 + (long)(e*NN + n) * C1;
    if (deg == 0) { out[c] = 0.f; return; }

    const int*   sr = g_srcs + e*NE + off;
    const float* w  = g_w1 + (long)(e*NE + off) * H1;
    const float* hsrc = g_h1 + c_SRC[e]*NN*C1;

    float accv = 0.f;
    int i = 0;
    for (; i + 2 <= deg; i += 2) {
        int   r0 = sr[i],            r1 = sr[i+1];
        float w0 = w[i*H1 + h],      w1 = w[(i+1)*H1 + h];
        accv += w0 * hsrc[r0*C1 + c];
        accv += w1 * hsrc[r1*C1 + c];
    }
    if (i < deg)
        accv += w[i*H1 + h] * hsrc[sr[i]*C1 + c];
    out[c] = fmaxf(accv, 0.f);
}

// ---------------------------------------------------------------------------
// Semantic score + group softmax (tiny)
// ---------------------------------------------------------------------------
__global__ void k_score1(const float* __restrict__ q) {
    __shared__ float red[128];
    __shared__ float sc[NR];
    int t = threadIdx.x;
    for (int e = 0; e < NR; e++) {
        float p = q[t] * g_colsum1[e*C1 + t];
        red[t] = p; __syncthreads();
        for (int s = 64; s > 0; s >>= 1) {
            if (t < s) red[t] += red[t + s];
            __syncthreads();
        }
        if (t == 0) sc[e] = red[0] / (float)NN;
        __syncthreads();
    }
    if (t < NT) {
        int b = c_GRPOFF[t], e2 = c_GRPOFF[t+1];
        float m = -1e30f;
        for (int g = b; g < e2; g++) m = fmaxf(m, sc[c_GRP[g]]);
        float ssum = 0.f;
        for (int g = b; g < e2; g++) ssum += expf(sc[c_GRP[g]] - m);
        for (int g = b; g < e2; g++)
            g_sattn1[c_GRP[g]] = expf(sc[c_GRP[g]] - m) / ssum;
    }
}

__global__ void k_score2(const float* __restrict__ q) {
    __shared__ float red[128];
    __shared__ float sc[NR];
    int t = threadIdx.x;
    for (int e = 0; e < NR; e++) {
        float p = (t < C2) ? q[t] * g_colsum2[e*C2 + t] : 0.f;
        red[t] = p; __syncthreads();
        for (int s = 64; s > 0; s >>= 1) {
            if (t < s) red[t] += red[t + s];
            __syncthreads();
        }
        if (t == 0) sc[e] = red[0] / (float)NN;
        __syncthreads();
    }
    if (t < NT) {
        int b = c_GRPOFF[t], e2 = c_GRPOFF[t+1];
        float m = -1e30f;
        for (int g = b; g < e2; g++) m = fmaxf(m, sc[c_GRP[g]]);
        float ssum = 0.f;
        for (int g = b; g < e2; g++) ssum += expf(sc[c_GRP[g]] - m);
        for (int g = b; g < e2; g++)
            g_sattn2[c_GRP[g]] = expf(sc[c_GRP[g]] - m) / ssum;
    }
}

// ---------------------------------------------------------------------------
// Fuse relations per dst type (layer1) + elu -> x2
// ---------------------------------------------------------------------------
__global__ void k_combine1() {
    long idx = (long)blockIdx.x * blockDim.x + threadIdx.x;
    if (idx >= (long)NT*NN*C1) return;
    int t  = (int)(idx / (NN*C1));
    int nc = (int)(idx - (long)t*NN*C1);
    float v = 0.f;
    for (int g = c_GRPOFF[t]; g < c_GRPOFF[t+1]; g++) {
        int e = c_GRP[g];
        v += g_sattn1[e] * g_out1[(long)e*NN*C1 + nc];
    }
    g_x2[idx] = v > 0.f ? v : expf(v) - 1.f;
}

// ---------------------------------------------------------------------------
// Layer 2 logits (H=1): warp per (relation, node)
// ---------------------------------------------------------------------------
__global__ void k_logits2(const float* __restrict__ att_src,
                          const float* __restrict__ att_dst)
{
    int e = blockIdx.y;
    int n = blockIdx.x * 8 + (threadIdx.x >> 5);
    if (n >= NN) return;
    int l = threadIdx.x & 31;
    float ps = g_h2[c_SRC[e]*NN*C2 + n*C2 + l] * att_src[e*C2 + l];
    float pd = g_h2[c_DST[e]*NN*C2 + n*C2 + l] * att_dst[e*C2 + l];
#pragma unroll
    for (int o = 16; o > 0; o >>= 1) {
        ps += __shfl_xor_sync(0xffffffffu, ps, o);
        pd += __shfl_xor_sync(0xffffffffu, pd, o);
    }
    if (l == 0) { g_asrc2[e*NN + n] = ps; g_adst2[e*NN + n] = pd; }
}

// ---------------------------------------------------------------------------
// Segment softmax, layer 2: one warp per (relation, node), H=1.
// ---------------------------------------------------------------------------
__global__ void k_soft2() {
    int e = blockIdx.y;
    int n = blockIdx.x * 8 + (threadIdx.x >> 5);
    if (n >= NN) return;
    int l = threadIdx.x & 31;

    int off = g_offsets[e*(NN+1) + n];
    int deg = g_offsets[e*(NN+1) + n + 1] - off;
    if (deg == 0) return;

    const int*   sr  = g_srcs + e*NE + off;
    const float* asr = g_asrc2 + e*NN;
    float ad = g_adst2[e*NN + n];

    float m = -1e30f, s = 0.f;
    for (int i = l; i < deg; i += 32) {
        float a = asr[sr[i]] + ad;
        a = a > 0.f ? a : 0.2f * a;
        if (a > m) { s = s * expf(m - a) + 1.f; m = a; }
        else        s += expf(a - m);
    }
#pragma unroll
    for (int o = 1; o <= 16; o <<= 1) {
        float mo = __shfl_xor_sync(0xffffffffu, m, o);
        float so = __shfl_xor_sync(0xffffffffu, s, o);
        float mn = fmaxf(m, mo);
        s = s * expf(m - mn) + so * expf(mo - mn);
        m = mn;
    }
    float inv = 1.f / (s + 1e-16f);
    float* w = g_w2 + e*NE + off;
    for (int i = l; i < deg; i += 32) {
        float a = asr[sr[i]] + ad;
        a = a > 0.f ? a : 0.2f * a;
        w[i] = expf(a - m) * inv;
    }
}

// ---------------------------------------------------------------------------
// Aggregation layer 2: warp per (node, relation), weighted gather only.
// ---------------------------------------------------------------------------
__global__ void k_agg2() {
    int e = blockIdx.y;
    int n = blockIdx.x * 4 + (threadIdx.x >> 5);
    if (n >= NN) return;
    int c = threadIdx.x & 31;
    int off = g_offsets[e*(NN+1) + n];
    int deg = g_offsets[e*(NN+1) + n + 1] - off;
    float* out = g_out2 + (long)(e*NN + n) * C2;
    if (deg == 0) { out[c] = 0.f; return; }

    const int*   sr = g_srcs + e*NE + off;
    const float* w  = g_w2 + e*NE + off;
    const float* hsrc = g_h2 + c_SRC[e]*NN*C2;

    float accv = 0.f;
    int i = 0;
    for (; i + 2 <= deg; i += 2) {
        accv += w[i]   * hsrc[sr[i]*C2 + c];
        accv += w[i+1] * hsrc[sr[i+1]*C2 + c];
    }
    if (i < deg)
        accv += w[i] * hsrc[sr[i]*C2 + c];
    out[c] = fmaxf(accv, 0.f);
}

// ---------------------------------------------------------------------------
// Fuse relations layer 2 + final per-node channel softmax -> d_out
// ---------------------------------------------------------------------------
__global__ void k_combine2(float* __restrict__ out) {
    int g = blockIdx.x * 8 + (threadIdx.x >> 5);
    if (g >= NT*NN) return;
    int t = g / NN, n = g - t*NN;
    int c = threadIdx.x & 31;
    float v = 0.f;
    for (int gi = c_GRPOFF[t]; gi < c_GRPOFF[t+1]; gi++) {
        int e = c_GRP[gi];
        v += g_sattn2[e] * g_out2[(long)(e*NN + n)*C2 + c];
    }
    float m = v;
#pragma unroll
    for (int o = 16; o > 0; o >>= 1)
        m = fmaxf(m, __shfl_xor_sync(0xffffffffu, m, o));
    float ex = expf(v - m);
    float s = ex;
#pragma unroll
    for (int o = 16; o > 0; o >>= 1)
        s += __shfl_xor_sync(0xffffffffu, s, o);
    out[(long)g*C2 + c] = ex / s;
}

// ---------------------------------------------------------------------------
// Host launcher
// ---------------------------------------------------------------------------
extern "C" void kernel_launch(void* const* d_in, const int* in_sizes, int n_in,
                              void* d_out, int out_size)
{
    const float* x[4] = {(const float*)d_in[0], (const float*)d_in[1],
                         (const float*)d_in[2], (const float*)d_in[3]};
    const int*   edges    = (const int*)  d_in[4];
    const float* proj1_W  = (const float*)d_in[5];
    const float* proj1_b  = (const float*)d_in[6];
    const float* att1_src = (const float*)d_in[7];
    const float* att1_dst = (const float*)d_in[8];
    const float* k1_W     = (const float*)d_in[9];
    const float* k1_b     = (const float*)d_in[10];
    const float* q1       = (const float*)d_in[11];
    const float* proj2_W  = (const float*)d_in[12];
    const float* proj2_b  = (const float*)d_in[13];
    const float* att2_src = (const float*)d_in[14];
    const float* att2_dst = (const float*)d_in[15];
    const float* k2_W     = (const float*)d_in[16];
    const float* k2_b     = (const float*)d_in[17];
    const float* q2       = (const float*)d_in[18];
    float* out = (float*)d_out;

    float *h1p, *x2p, *h2p, *out1p, *out2p, *cs1p, *cs2p;
    cudaGetSymbolAddress((void**)&h1p,   g_h1);
    cudaGetSymbolAddress((void**)&x2p,   g_x2);
    cudaGetSymbolAddress((void**)&h2p,   g_h2);
    cudaGetSymbolAddress((void**)&out1p, g_out1);
    cudaGetSymbolAddress((void**)&out2p, g_out2);
    cudaGetSymbolAddress((void**)&cs1p,  g_colsum1);
    cudaGetSymbolAddress((void**)&cs2p,  g_colsum2);

    const int MT = (NN + 127) / 128;   // 235 row tiles

    // zero counts/colsums, build CSR (shared by both layers)
    k_zero <<<(NR*NN + 255)/256, 256>>>();
    k_count<<<(NR*NE + 255)/256, 256>>>(edges);
    k_scan <<<NR, 1024>>>();
    k_fill <<<(NR*NE + 255)/256, 256>>>(edges);

    // ---- layer 1 ----
    for (int t = 0; t < NT; t++)
        k_gemm<0><<<dim3(MT, 1, 1), 256>>>(
            x[t], proj1_W + (long)t*IN1*C1, proj1_b + t*C1,
            h1p + (long)t*NN*C1, NN, C1, IN1, 0, 0, nullptr, 0);

    k_logits1<<<dim3((NN + 7)/8, NR), 256>>>(att1_src, att1_dst);
    k_soft1  <<<dim3((NN + 7)/8, NR), 256>>>();
    k_agg1   <<<dim3(NN, NR), 128>>>();

    k_gemm<1><<<dim3(MT, 1, NR), 256>>>(
        out1p, k1_W, k1_b, nullptr, NN, C1, C1,
        (long)NN*C1, 0, cs1p, C1);
    k_score1<<<1, 128>>>(q1);
    k_combine1<<<((long)NT*NN*C1 + 255)/256, 256>>>();

    // ---- layer 2 ----
    for (int t = 0; t < NT; t++)
        k_gemm<0><<<dim3(MT, 1, 1), 256>>>(
            x2p + (long)t*NN*C1, proj2_W + (long)t*C1*C2, proj2_b + t*C2,
            h2p + (long)t*NN*C2, NN, C2, C1, 0, 0, nullptr, 0);

    k_logits2<<<dim3((NN + 7)/8, NR), 256>>>(att2_src, att2_dst);
    k_soft2  <<<dim3((NN + 7)/8, NR), 256>>>();
    k_agg2   <<<dim3((NN + 3)/4, NR), 128>>>();

    k_gemm<1><<<dim3(MT, 1, NR), 256>>>(
        out2p, k2_W, k2_b, nullptr, NN, C2, C2,
        (long)NN*C2, 0, cs2p, C2);
    k_score2<<<1, 128>>>(q2);

    k_combine2<<<(NT*NN + 7)/8, 256>>>(out);
}